// round 3
// baseline (speedup 1.0000x reference)
#include <cuda_runtime.h>
#include <math.h>

// Problem constants
#define B_SZ 256
#define T_SZ 96
#define F_DIM 368
#define D_MODEL 368
#define G3 1104          // 3*D_MODEL
#define NCLS 29
#define NOUT 31          // 2 coarse + 29 fine
#define M_ROWS 24576     // B*T

// -------- device scratch (static __device__ arrays; no allocation) --------
__device__ float g_xproj[(size_t)M_ROWS * G3];                 // (B*T, 3D)
__device__ float g_xprojT[(size_t)T_SZ * D_MODEL * 3 * B_SZ];  // [t][u][g][b]
__device__ float g_h[(size_t)T_SZ * D_MODEL * B_SZ];           // [t][d][b]
__device__ float g_temporal[(size_t)M_ROWS * D_MODEL];         // (B,T,D)
__device__ float g_logits[(size_t)M_ROWS * NOUT];

// ============================================================
// Kernel 1: xproj = features @ Wi^T + bi   (M=24576, N=1104, K=368)
// ============================================================
__global__ void xproj_kernel(const float* __restrict__ A,
                             const float* __restrict__ W,
                             const float* __restrict__ bi)
{
    __shared__ float As[16][128];
    __shared__ float Bs[16][64];

    const int m0 = blockIdx.y * 128;
    const int n0 = blockIdx.x * 64;
    const int tid = threadIdx.x;
    const int tx = tid & 15;
    const int ty = tid >> 4;

    float acc[8][4];
#pragma unroll
    for (int i = 0; i < 8; i++)
#pragma unroll
        for (int j = 0; j < 4; j++) acc[i][j] = 0.f;

    for (int k0 = 0; k0 < F_DIM; k0 += 16) {
#pragma unroll
        for (int l = 0; l < 2; l++) {
            int idx = tid + l * 256;
            int row = idx >> 2, kq = idx & 3;
            float4 v = *(const float4*)(A + (size_t)(m0 + row) * F_DIM + k0 + kq * 4);
            As[kq * 4 + 0][row] = v.x;
            As[kq * 4 + 1][row] = v.y;
            As[kq * 4 + 2][row] = v.z;
            As[kq * 4 + 3][row] = v.w;
        }
        {
            int row = tid >> 2, kq = tid & 3;
            int n = n0 + row;
            float4 v = make_float4(0.f, 0.f, 0.f, 0.f);
            if (n < G3)
                v = *(const float4*)(W + (size_t)n * F_DIM + k0 + kq * 4);
            Bs[kq * 4 + 0][row] = v.x;
            Bs[kq * 4 + 1][row] = v.y;
            Bs[kq * 4 + 2][row] = v.z;
            Bs[kq * 4 + 3][row] = v.w;
        }
        __syncthreads();
#pragma unroll
        for (int k = 0; k < 16; k++) {
            float a[8], b[4];
#pragma unroll
            for (int i = 0; i < 8; i++) a[i] = As[k][ty * 8 + i];
#pragma unroll
            for (int j = 0; j < 4; j++) b[j] = Bs[k][tx * 4 + j];
#pragma unroll
            for (int i = 0; i < 8; i++)
#pragma unroll
                for (int j = 0; j < 4; j++) acc[i][j] += a[i] * b[j];
        }
        __syncthreads();
    }

    float bv[4];
#pragma unroll
    for (int j = 0; j < 4; j++) {
        int n = n0 + tx * 4 + j;
        bv[j] = (n < G3) ? bi[n] : 0.f;
    }
#pragma unroll
    for (int i = 0; i < 8; i++) {
        int m = m0 + ty * 8 + i;
#pragma unroll
        for (int j = 0; j < 4; j++) {
            int n = n0 + tx * 4 + j;
            if (n < G3) g_xproj[(size_t)m * G3 + n] = acc[i][j] + bv[j];
        }
    }
}

// ============================================================
// Kernel 1b: transpose xproj (b,t,g,u) -> xprojT [t][u][g][b]
// ============================================================
__global__ void xprojT_kernel()
{
    __shared__ float tile[32][33];
    const int t = blockIdx.x;
    const int u0 = blockIdx.y * 32;
    const int b0 = blockIdx.z * 32;
    const int tx = threadIdx.x, ty = threadIdx.y;

    for (int g = 0; g < 3; g++) {
        for (int bb = ty; bb < 32; bb += 8) {
            int u = u0 + tx;
            float v = 0.f;
            if (u < D_MODEL)
                v = g_xproj[((size_t)(b0 + bb) * T_SZ + t) * G3 + g * D_MODEL + u];
            tile[tx][bb] = v;
        }
        __syncthreads();
        for (int ur = ty; ur < 32; ur += 8) {
            int u = u0 + ur;
            if (u < D_MODEL)
                g_xprojT[(((size_t)t * D_MODEL + u) * 3 + g) * B_SZ + b0 + tx] = tile[ur][tx];
        }
        __syncthreads();
    }
}

// ============================================================
// Kernel 2: one GRU time step.
// grid = 128 = 16 unit-groups(23 units) x 8 batch-groups(32 batches)
// 256 threads = 8 warps (2 per SMSP). warp w owns units u0 + w*3 + {0,1,2};
// lane = batch. Thread tile: 3 units x 3 gates x 1 batch = 9 accumulators.
// Weight LDS are warp-broadcast; h LDS are lane-consecutive (conflict-free).
// smem: wh_s[72][368] (row = ul*3+g), h_s[368][36]
// ============================================================
#define WH_STRIDE 368
#define HS_STRIDE 36
#define GRU_SMEM ((72 * WH_STRIDE + D_MODEL * HS_STRIDE) * 4)

__global__ __launch_bounds__(256, 1)
void gru_step_kernel(const float* __restrict__ Wh,
                     const float* __restrict__ bh, int t)
{
    extern __shared__ float sm[];
    float* wh_s = sm;                      // [72][368]
    float* h_s  = sm + 72 * WH_STRIDE;     // [368][36]

    const int tid = threadIdx.x;
    const int bg = blockIdx.x & 7;
    const int ug = blockIdx.x >> 3;
    const int b0 = bg * 32;
    const int u0 = ug * 23;
    const int tu = tid >> 5;    // warp id 0..7 -> 3 units each
    const int lane = tid & 31;  // batch lane

    // fill wh_s: rows = (ul*3+g), ul<23 real, ul=23 zero pad (row 69..71)
    for (int idx = tid; idx < 72 * 92; idx += 256) {
        int r = idx / 92, q = idx - r * 92;
        int ul = r / 3, g = r - ul * 3;
        float4 v = make_float4(0.f, 0.f, 0.f, 0.f);
        if (ul < 23)
            v = *(const float4*)(Wh + ((size_t)(g * D_MODEL + u0 + ul)) * D_MODEL + q * 4);
        *(float4*)(wh_s + r * WH_STRIDE + q * 4) = v;
    }
    // fill h_s: coalesced copy of h_{t-1}[all 368 units][our 32 batches]
    if (t > 0) {
        const float* hp = g_h + (size_t)(t - 1) * D_MODEL * B_SZ;
        for (int idx = tid; idx < D_MODEL * 8; idx += 256) {
            int u = idx >> 3, c = idx & 7;
            float4 v = *(const float4*)(hp + (size_t)u * B_SZ + b0 + c * 4);
            *(float4*)(h_s + u * HS_STRIDE + c * 4) = v;
        }
    }
    __syncthreads();

    float acc[9];
#pragma unroll
    for (int r = 0; r < 9; r++) acc[r] = 0.f;

    if (t > 0) {
        const float* wbase = wh_s + tu * 9 * WH_STRIDE;  // 9 consecutive rows
        const float* hcol = h_s + lane;
#pragma unroll 4
        for (int k = 0; k < D_MODEL; k++) {
            float hv = hcol[k * HS_STRIDE];
#pragma unroll
            for (int r = 0; r < 9; r++)
                acc[r] += wbase[r * WH_STRIDE + k] * hv;
        }
    }

    // gate math + write h_t to g_h[t][d][b]
    const float* xT = g_xprojT + (size_t)t * D_MODEL * 3 * B_SZ;
    float* hout = g_h + (size_t)t * D_MODEL * B_SZ;
    const int b = b0 + lane;
#pragma unroll
    for (int j = 0; j < 3; j++) {
        int ul = tu * 3 + j;
        if (ul < 23) {
            int d = u0 + ul;
            float ghr = acc[j * 3 + 0] + bh[d];
            float ghz = acc[j * 3 + 1] + bh[D_MODEL + d];
            float ghn = acc[j * 3 + 2] + bh[2 * D_MODEL + d];
            float gir = xT[((size_t)d * 3 + 0) * B_SZ + b];
            float giz = xT[((size_t)d * 3 + 1) * B_SZ + b];
            float gin = xT[((size_t)d * 3 + 2) * B_SZ + b];
            float rr = 1.f / (1.f + expf(-(gir + ghr)));
            float zz = 1.f / (1.f + expf(-(giz + ghz)));
            float nn = tanhf(gin + rr * ghn);
            float hprev = (t > 0) ? h_s[d * HS_STRIDE + lane] : 0.f;
            hout[(size_t)d * B_SZ + b] = (1.f - zz) * nn + zz * hprev;
        }
    }
}

// ============================================================
// Kernel 2b: transpose g_h [t][d][b] -> g_temporal (b,t,d)
// ============================================================
__global__ void hT_kernel()
{
    __shared__ float tile[32][33];
    const int t = blockIdx.x;
    const int d0 = blockIdx.y * 32;
    const int b0 = blockIdx.z * 32;
    const int tx = threadIdx.x, ty = threadIdx.y;

    for (int dr = ty; dr < 32; dr += 8) {
        int d = d0 + dr;
        float v = 0.f;
        if (d < D_MODEL)
            v = g_h[((size_t)t * D_MODEL + d) * B_SZ + b0 + tx];
        tile[dr][tx] = v;
    }
    __syncthreads();
    for (int br = ty; br < 32; br += 8) {
        int d = d0 + tx;
        if (d < D_MODEL)
            g_temporal[((size_t)(b0 + br) * T_SZ + t) * D_MODEL + d] = tile[tx][br];
    }
}

// ============================================================
// Kernel 3: logits = temporal @ [Wc;Wf]^T + [bc;bf]
// ============================================================
#define HEAD_SMEM ((31 * 368 + 256 * 93) * 4)

__global__ void head_kernel(const float* __restrict__ Wc,
                            const float* __restrict__ bc,
                            const float* __restrict__ Wf,
                            const float* __restrict__ bf)
{
    extern __shared__ float sm[];
    float* W_s = sm;               // [31][368]
    float* A_s = sm + 31 * 368;    // [256][93]

    const int m0 = blockIdx.x * 256;
    const int tid = threadIdx.x;

    for (int idx = tid; idx < 31 * 92; idx += 128) {
        int row = idx / 92, kq = idx % 92;
        const float* src = (row < 2) ? (Wc + (size_t)row * D_MODEL)
                                     : (Wf + (size_t)(row - 2) * D_MODEL);
        float4 v = *(const float4*)(src + kq * 4);
        *(float4*)(W_s + row * D_MODEL + kq * 4) = v;
    }

    float acc0[NOUT], acc1[NOUT];
#pragma unroll
    for (int o = 0; o < NOUT; o++) { acc0[o] = 0.f; acc1[o] = 0.f; }

    for (int c = 0; c < 4; c++) {
        __syncthreads();
        for (int idx = tid; idx < 256 * 23; idx += 128) {
            int row = idx / 23, kq = idx % 23;
            float4 v = *(const float4*)(g_temporal +
                         (size_t)(m0 + row) * D_MODEL + c * 92 + kq * 4);
            float* dst = A_s + row * 93 + kq * 4;
            dst[0] = v.x; dst[1] = v.y; dst[2] = v.z; dst[3] = v.w;
        }
        __syncthreads();
#pragma unroll 4
        for (int k = 0; k < 92; k++) {
            float a0 = A_s[tid * 93 + k];
            float a1 = A_s[(tid + 128) * 93 + k];
#pragma unroll
            for (int o = 0; o < NOUT; o++) {
                float w = W_s[o * D_MODEL + c * 92 + k];
                acc0[o] += a0 * w;
                acc1[o] += a1 * w;
            }
        }
    }

#pragma unroll
    for (int o = 0; o < NOUT; o++) {
        float bias = (o < 2) ? bc[o] : bf[o - 2];
        g_logits[(size_t)(m0 + tid) * NOUT + o] = acc0[o] + bias;
        g_logits[(size_t)(m0 + tid + 128) * NOUT + o] = acc1[o] + bias;
    }
}

// ============================================================
// Kernel 4: softmax + sigmoid + NMS + argmax
// ============================================================
__global__ void finalize_kernel(float* __restrict__ out)
{
    __shared__ float bg_s[T_SZ];
    const int b = blockIdx.x;
    const int t = threadIdx.x;
    const size_t mi = (size_t)b * T_SZ + t;
    const float* L = g_logits + mi * NOUT;

    float l0 = L[0], l1 = L[1];
    float mx = fmaxf(l0, l1);
    float e0 = expf(l0 - mx), e1 = expf(l1 - mx);
    float inv = 1.f / (e0 + e1);
    float s0 = e0 * inv, s1 = e1 * inv;
    bg_s[t] = s0;

#pragma unroll
    for (int j = 0; j < NCLS; j++) {
        float v = 1.f / (1.f + expf(-L[2 + j]));
        out[(size_t)M_ROWS * 3 + mi * NCLS + j] = v;
    }
    __syncthreads();

    float wmin = s0;
#pragma unroll
    for (int dt = -2; dt <= 2; dt++) {
        int tt = t + dt;
        if (tt >= 0 && tt < T_SZ) wmin = fminf(wmin, bg_s[tt]);
    }
    bool keep = (s0 == wmin);
    float n0 = keep ? s0 : 0.f;
    float n1 = keep ? s1 : 0.f;

    out[mi] = (n1 > n0) ? 1.f : 0.f;
    out[M_ROWS + mi * 2 + 0] = n0;
    out[M_ROWS + mi * 2 + 1] = n1;
}

// ============================================================
extern "C" void kernel_launch(void* const* d_in, const int* in_sizes, int n_in,
                              void* d_out, int out_size)
{
    const float* features = (const float*)d_in[0];
    // d_in[1] = hand (unused)
    const float* Wi = (const float*)d_in[2];
    const float* Wh = (const float*)d_in[3];
    const float* bi = (const float*)d_in[4];
    const float* bh = (const float*)d_in[5];
    const float* Wc = (const float*)d_in[6];
    const float* bc = (const float*)d_in[7];
    const float* Wf = (const float*)d_in[8];
    const float* bf = (const float*)d_in[9];
    float* out = (float*)d_out;

    cudaFuncSetAttribute(gru_step_kernel,
                         cudaFuncAttributeMaxDynamicSharedMemorySize, GRU_SMEM);
    cudaFuncSetAttribute(head_kernel,
                         cudaFuncAttributeMaxDynamicSharedMemorySize, HEAD_SMEM);

    // 1) input projection + transpose to [t][u][g][b]
    dim3 xg((G3 + 63) / 64, M_ROWS / 128);
    xproj_kernel<<<xg, 256>>>(features, Wi, bi);
    xprojT_kernel<<<dim3(T_SZ, 12, 8), dim3(32, 8)>>>();

    // 2) recurrence: 96 sequential steps, 2 warps/SMSP
    for (int t = 0; t < T_SZ; t++)
        gru_step_kernel<<<128, 256, GRU_SMEM>>>(Wh, bh, t);

    // 2b) transpose hidden states to (b,t,d) for heads
    hT_kernel<<<dim3(T_SZ, 12, 8), dim3(32, 8)>>>();

    // 3) output heads
    head_kernel<<<M_ROWS / 256, 128, HEAD_SMEM>>>(Wc, bc, Wf, bf);

    // 4) softmax/sigmoid/NMS/argmax
    finalize_kernel<<<B_SZ, T_SZ>>>(out);
}

// round 4
// speedup vs baseline: 1.0804x; 1.0804x over previous
#include <cuda_runtime.h>
#include <math.h>

// Problem constants
#define B_SZ 256
#define T_SZ 96
#define F_DIM 368
#define D_MODEL 368
#define G3 1104          // 3*D_MODEL
#define NCLS 29
#define NOUT 31          // 2 coarse + 29 fine
#define M_ROWS 24576     // B*T

// -------- device scratch (static __device__ arrays; no allocation) --------
__device__ float g_xproj[(size_t)M_ROWS * G3];                 // (B*T, 3D)
__device__ float g_xprojT[(size_t)T_SZ * D_MODEL * 3 * B_SZ];  // [t][u][g][b]
__device__ float g_h[(size_t)T_SZ * D_MODEL * B_SZ];           // [t][d][b]
__device__ float g_temporal[(size_t)M_ROWS * D_MODEL];         // (B,T,D)
__device__ float g_logits[(size_t)M_ROWS * NOUT];

// ============================================================
// Kernel 1: xproj = features @ Wi^T + bi   (M=24576, N=1104, K=368)
// ============================================================
__global__ void xproj_kernel(const float* __restrict__ A,
                             const float* __restrict__ W,
                             const float* __restrict__ bi)
{
    __shared__ float As[16][128];
    __shared__ float Bs[16][64];

    const int m0 = blockIdx.y * 128;
    const int n0 = blockIdx.x * 64;
    const int tid = threadIdx.x;
    const int tx = tid & 15;
    const int ty = tid >> 4;

    float acc[8][4];
#pragma unroll
    for (int i = 0; i < 8; i++)
#pragma unroll
        for (int j = 0; j < 4; j++) acc[i][j] = 0.f;

    for (int k0 = 0; k0 < F_DIM; k0 += 16) {
#pragma unroll
        for (int l = 0; l < 2; l++) {
            int idx = tid + l * 256;
            int row = idx >> 2, kq = idx & 3;
            float4 v = *(const float4*)(A + (size_t)(m0 + row) * F_DIM + k0 + kq * 4);
            As[kq * 4 + 0][row] = v.x;
            As[kq * 4 + 1][row] = v.y;
            As[kq * 4 + 2][row] = v.z;
            As[kq * 4 + 3][row] = v.w;
        }
        {
            int row = tid >> 2, kq = tid & 3;
            int n = n0 + row;
            float4 v = make_float4(0.f, 0.f, 0.f, 0.f);
            if (n < G3)
                v = *(const float4*)(W + (size_t)n * F_DIM + k0 + kq * 4);
            Bs[kq * 4 + 0][row] = v.x;
            Bs[kq * 4 + 1][row] = v.y;
            Bs[kq * 4 + 2][row] = v.z;
            Bs[kq * 4 + 3][row] = v.w;
        }
        __syncthreads();
#pragma unroll
        for (int k = 0; k < 16; k++) {
            float a[8], b[4];
#pragma unroll
            for (int i = 0; i < 8; i++) a[i] = As[k][ty * 8 + i];
#pragma unroll
            for (int j = 0; j < 4; j++) b[j] = Bs[k][tx * 4 + j];
#pragma unroll
            for (int i = 0; i < 8; i++)
#pragma unroll
                for (int j = 0; j < 4; j++) acc[i][j] += a[i] * b[j];
        }
        __syncthreads();
    }

    float bv[4];
#pragma unroll
    for (int j = 0; j < 4; j++) {
        int n = n0 + tx * 4 + j;
        bv[j] = (n < G3) ? bi[n] : 0.f;
    }
#pragma unroll
    for (int i = 0; i < 8; i++) {
        int m = m0 + ty * 8 + i;
#pragma unroll
        for (int j = 0; j < 4; j++) {
            int n = n0 + tx * 4 + j;
            if (n < G3) g_xproj[(size_t)m * G3 + n] = acc[i][j] + bv[j];
        }
    }
}

// ============================================================
// Kernel 1b: transpose xproj (b,t,g,u) -> xprojT [t][u][g][b]
// ============================================================
__global__ void xprojT_kernel()
{
    __shared__ float tile[32][33];
    const int t = blockIdx.x;
    const int u0 = blockIdx.y * 32;
    const int b0 = blockIdx.z * 32;
    const int tx = threadIdx.x, ty = threadIdx.y;

    for (int g = 0; g < 3; g++) {
        for (int bb = ty; bb < 32; bb += 8) {
            int u = u0 + tx;
            float v = 0.f;
            if (u < D_MODEL)
                v = g_xproj[((size_t)(b0 + bb) * T_SZ + t) * G3 + g * D_MODEL + u];
            tile[tx][bb] = v;
        }
        __syncthreads();
        for (int ur = ty; ur < 32; ur += 8) {
            int u = u0 + ur;
            if (u < D_MODEL)
                g_xprojT[(((size_t)t * D_MODEL + u) * 3 + g) * B_SZ + b0 + tx] = tile[ur][tx];
        }
        __syncthreads();
    }
}

// ============================================================
// Kernel 2: one GRU time step, k-split GEMM.
// grid = 128 = 32 unit-groups(12 units = 36 gate-rows) x 4 batch-groups(64)
// 256 threads: tid = kq*64 + rg*16 + bg
//   kq in [0,4): k-chunk of 92;  rg in [0,4): 9 rows (3 units);  bg in [0,16): 4 batches
// inner loop per k: 36 FFMA, 9 broadcast w-LDS + 1 LDS.128 h.
// smem: wh_s[36][368] + h_s[368][68]; kq-partials reduced through wh_s region.
// ============================================================
#define HS_STRIDE 68
#define WH_FLOATS (36 * 368)
#define GRU_SMEM ((WH_FLOATS + D_MODEL * HS_STRIDE) * 4)

__global__ __launch_bounds__(256, 1)
void gru_step_kernel(const float* __restrict__ Wh,
                     const float* __restrict__ bh, int t)
{
    extern __shared__ float sm[];
    float* wh_s = sm;                      // [36][368], later reused for partials
    float* h_s  = sm + WH_FLOATS;          // [368][68]

    const int tid = threadIdx.x;
    const int ug = blockIdx.x >> 2;        // 0..31
    const int bgi = blockIdx.x & 3;        // 0..3
    const int b0 = bgi * 64;
    const int u_base = ug * 12;

    const int kq = tid >> 6;               // 0..3
    const int rg = (tid >> 4) & 3;         // 0..3
    const int bg = tid & 15;               // 0..15

    // fill wh_s: rows r = ul*3+g (ul 0..11), zero-pad units >= 368
    for (int idx = tid; idx < 36 * 92; idx += 256) {
        int r = idx / 92, q = idx - r * 92;
        int ul = r / 3, g = r - ul * 3;
        int u = u_base + ul;
        float4 v = make_float4(0.f, 0.f, 0.f, 0.f);
        if (u < D_MODEL)
            v = *(const float4*)(Wh + ((size_t)(g * D_MODEL + u)) * D_MODEL + q * 4);
        *(float4*)(wh_s + r * 368 + q * 4) = v;
    }
    // fill h_s: h_{t-1}[368 units][64 batches]
    if (t > 0) {
        const float* hp = g_h + (size_t)(t - 1) * D_MODEL * B_SZ;
        for (int idx = tid; idx < D_MODEL * 16; idx += 256) {
            int u = idx >> 4, c = idx & 15;
            float4 v = *(const float4*)(hp + (size_t)u * B_SZ + b0 + c * 4);
            *(float4*)(h_s + u * HS_STRIDE + c * 4) = v;
        }
    }
    __syncthreads();

    float acc[9][4];
#pragma unroll
    for (int j = 0; j < 9; j++)
#pragma unroll
        for (int c = 0; c < 4; c++) acc[j][c] = 0.f;

    if (t > 0) {
        const float* wp = wh_s + (rg * 9) * 368 + kq * 92;
        const float* hp = h_s + (kq * 92) * HS_STRIDE + bg * 4;
#pragma unroll 2
        for (int k = 0; k < 92; k++) {
            float4 hv = *(const float4*)(hp + k * HS_STRIDE);
#pragma unroll
            for (int j = 0; j < 9; j++) {
                float w = wp[j * 368 + k];
                acc[j][0] += w * hv.x;
                acc[j][1] += w * hv.y;
                acc[j][2] += w * hv.z;
                acc[j][3] += w * hv.w;
            }
        }
    }

    // kq-partial reduction through smem (reuse wh_s region; weights done)
    __syncthreads();
    const int t2 = rg * 16 + bg;           // 0..63
    if (kq > 0) {
        float* dst = wh_s + ((kq - 1) * 64 + t2) * 36;
#pragma unroll
        for (int j = 0; j < 9; j++)
            *(float4*)(dst + j * 4) = make_float4(acc[j][0], acc[j][1], acc[j][2], acc[j][3]);
    }
    __syncthreads();

    if (kq == 0) {
#pragma unroll
        for (int q = 0; q < 3; q++) {
            const float* src = wh_s + (q * 64 + t2) * 36;
#pragma unroll
            for (int j = 0; j < 9; j++) {
                float4 v = *(const float4*)(src + j * 4);
                acc[j][0] += v.x; acc[j][1] += v.y; acc[j][2] += v.z; acc[j][3] += v.w;
            }
        }

        // gate math for 3 units x 4 batches
        const float* xT = g_xprojT + (size_t)t * D_MODEL * 3 * B_SZ;
        float* hout = g_h + (size_t)t * D_MODEL * B_SZ;
#pragma unroll
        for (int ul3 = 0; ul3 < 3; ul3++) {
            int d = u_base + rg * 3 + ul3;
            if (d < D_MODEL) {
                float bhr = bh[d];
                float bhz = bh[D_MODEL + d];
                float bhn = bh[2 * D_MODEL + d];
#pragma unroll
                for (int c = 0; c < 4; c++) {
                    int b = b0 + bg * 4 + c;
                    float ghr = acc[ul3 * 3 + 0][c] + bhr;
                    float ghz = acc[ul3 * 3 + 1][c] + bhz;
                    float ghn = acc[ul3 * 3 + 2][c] + bhn;
                    float gir = xT[((size_t)d * 3 + 0) * B_SZ + b];
                    float giz = xT[((size_t)d * 3 + 1) * B_SZ + b];
                    float gin = xT[((size_t)d * 3 + 2) * B_SZ + b];
                    float rr = 1.f / (1.f + expf(-(gir + ghr)));
                    float zz = 1.f / (1.f + expf(-(giz + ghz)));
                    float nn = tanhf(gin + rr * ghn);
                    float hprev = (t > 0) ? h_s[d * HS_STRIDE + bg * 4 + c] : 0.f;
                    hout[(size_t)d * B_SZ + b] = (1.f - zz) * nn + zz * hprev;
                }
            }
        }
    }
}

// ============================================================
// Kernel 2b: transpose g_h [t][d][b] -> g_temporal (b,t,d)
// ============================================================
__global__ void hT_kernel()
{
    __shared__ float tile[32][33];
    const int t = blockIdx.x;
    const int d0 = blockIdx.y * 32;
    const int b0 = blockIdx.z * 32;
    const int tx = threadIdx.x, ty = threadIdx.y;

    for (int dr = ty; dr < 32; dr += 8) {
        int d = d0 + dr;
        float v = 0.f;
        if (d < D_MODEL)
            v = g_h[((size_t)t * D_MODEL + d) * B_SZ + b0 + tx];
        tile[dr][tx] = v;
    }
    __syncthreads();
    for (int br = ty; br < 32; br += 8) {
        int d = d0 + tx;
        if (d < D_MODEL)
            g_temporal[((size_t)(b0 + br) * T_SZ + t) * D_MODEL + d] = tile[tx][br];
    }
}

// ============================================================
// Kernel 3: logits = temporal @ [Wc;Wf]^T + [bc;bf]
// ============================================================
#define HEAD_SMEM ((31 * 368 + 256 * 93) * 4)

__global__ void head_kernel(const float* __restrict__ Wc,
                            const float* __restrict__ bc,
                            const float* __restrict__ Wf,
                            const float* __restrict__ bf)
{
    extern __shared__ float sm[];
    float* W_s = sm;               // [31][368]
    float* A_s = sm + 31 * 368;    // [256][93]

    const int m0 = blockIdx.x * 256;
    const int tid = threadIdx.x;

    for (int idx = tid; idx < 31 * 92; idx += 128) {
        int row = idx / 92, kq = idx % 92;
        const float* src = (row < 2) ? (Wc + (size_t)row * D_MODEL)
                                     : (Wf + (size_t)(row - 2) * D_MODEL);
        float4 v = *(const float4*)(src + kq * 4);
        *(float4*)(W_s + row * D_MODEL + kq * 4) = v;
    }

    float acc0[NOUT], acc1[NOUT];
#pragma unroll
    for (int o = 0; o < NOUT; o++) { acc0[o] = 0.f; acc1[o] = 0.f; }

    for (int c = 0; c < 4; c++) {
        __syncthreads();
        for (int idx = tid; idx < 256 * 23; idx += 128) {
            int row = idx / 23, kq = idx % 23;
            float4 v = *(const float4*)(g_temporal +
                         (size_t)(m0 + row) * D_MODEL + c * 92 + kq * 4);
            float* dst = A_s + row * 93 + kq * 4;
            dst[0] = v.x; dst[1] = v.y; dst[2] = v.z; dst[3] = v.w;
        }
        __syncthreads();
#pragma unroll 4
        for (int k = 0; k < 92; k++) {
            float a0 = A_s[tid * 93 + k];
            float a1 = A_s[(tid + 128) * 93 + k];
#pragma unroll
            for (int o = 0; o < NOUT; o++) {
                float w = W_s[o * D_MODEL + c * 92 + k];
                acc0[o] += a0 * w;
                acc1[o] += a1 * w;
            }
        }
    }

#pragma unroll
    for (int o = 0; o < NOUT; o++) {
        float bias = (o < 2) ? bc[o] : bf[o - 2];
        g_logits[(size_t)(m0 + tid) * NOUT + o] = acc0[o] + bias;
        g_logits[(size_t)(m0 + tid + 128) * NOUT + o] = acc1[o] + bias;
    }
}

// ============================================================
// Kernel 4: softmax + sigmoid + NMS + argmax
// ============================================================
__global__ void finalize_kernel(float* __restrict__ out)
{
    __shared__ float bg_s[T_SZ];
    const int b = blockIdx.x;
    const int t = threadIdx.x;
    const size_t mi = (size_t)b * T_SZ + t;
    const float* L = g_logits + mi * NOUT;

    float l0 = L[0], l1 = L[1];
    float mx = fmaxf(l0, l1);
    float e0 = expf(l0 - mx), e1 = expf(l1 - mx);
    float inv = 1.f / (e0 + e1);
    float s0 = e0 * inv, s1 = e1 * inv;
    bg_s[t] = s0;

#pragma unroll
    for (int j = 0; j < NCLS; j++) {
        float v = 1.f / (1.f + expf(-L[2 + j]));
        out[(size_t)M_ROWS * 3 + mi * NCLS + j] = v;
    }
    __syncthreads();

    float wmin = s0;
#pragma unroll
    for (int dt = -2; dt <= 2; dt++) {
        int tt = t + dt;
        if (tt >= 0 && tt < T_SZ) wmin = fminf(wmin, bg_s[tt]);
    }
    bool keep = (s0 == wmin);
    float n0 = keep ? s0 : 0.f;
    float n1 = keep ? s1 : 0.f;

    out[mi] = (n1 > n0) ? 1.f : 0.f;
    out[M_ROWS + mi * 2 + 0] = n0;
    out[M_ROWS + mi * 2 + 1] = n1;
}

// ============================================================
extern "C" void kernel_launch(void* const* d_in, const int* in_sizes, int n_in,
                              void* d_out, int out_size)
{
    const float* features = (const float*)d_in[0];
    // d_in[1] = hand (unused)
    const float* Wi = (const float*)d_in[2];
    const float* Wh = (const float*)d_in[3];
    const float* bi = (const float*)d_in[4];
    const float* bh = (const float*)d_in[5];
    const float* Wc = (const float*)d_in[6];
    const float* bc = (const float*)d_in[7];
    const float* Wf = (const float*)d_in[8];
    const float* bf = (const float*)d_in[9];
    float* out = (float*)d_out;

    cudaFuncSetAttribute(gru_step_kernel,
                         cudaFuncAttributeMaxDynamicSharedMemorySize, GRU_SMEM);
    cudaFuncSetAttribute(head_kernel,
                         cudaFuncAttributeMaxDynamicSharedMemorySize, HEAD_SMEM);

    // 1) input projection + transpose to [t][u][g][b]
    dim3 xg((G3 + 63) / 64, M_ROWS / 128);
    xproj_kernel<<<xg, 256>>>(features, Wi, bi);
    xprojT_kernel<<<dim3(T_SZ, 12, 8), dim3(32, 8)>>>();

    // 2) recurrence: 96 sequential steps (k-split step GEMM)
    for (int t = 0; t < T_SZ; t++)
        gru_step_kernel<<<128, 256, GRU_SMEM>>>(Wh, bh, t);

    // 2b) transpose hidden states to (b,t,d) for heads
    hT_kernel<<<dim3(T_SZ, 12, 8), dim3(32, 8)>>>();

    // 3) output heads
    head_kernel<<<M_ROWS / 256, 128, HEAD_SMEM>>>(Wc, bc, Wf, bf);

    // 4) softmax/sigmoid/NMS/argmax
    finalize_kernel<<<B_SZ, T_SZ>>>(out);
}

// round 5
// speedup vs baseline: 1.3221x; 1.2237x over previous
#include <cuda_runtime.h>
#include <math.h>

// Problem constants
#define B_SZ 256
#define T_SZ 96
#define F_DIM 368
#define D_MODEL 368
#define G3 1104          // 3*D_MODEL
#define NCLS 29
#define NOUT 31          // 2 coarse + 29 fine
#define M_ROWS 24576     // B*T

// -------- device scratch (static __device__ arrays; no allocation) --------
__device__ float g_xproj[(size_t)M_ROWS * G3];                 // (B*T, 3D)
__device__ float g_xprojT[(size_t)T_SZ * D_MODEL * 3 * B_SZ];  // [t][u][g][b]
__device__ float g_h[(size_t)T_SZ * D_MODEL * B_SZ];           // [t][d][b]
__device__ float g_temporal[(size_t)M_ROWS * D_MODEL];         // (B,T,D)
__device__ float g_logits[(size_t)M_ROWS * NOUT];
__device__ unsigned g_bar;                                     // grid barrier counter

// -------- packed f32x2 helpers (Blackwell FFMA2) --------
__device__ __forceinline__ unsigned long long dup_f32(float f) {
    unsigned long long r;
    asm("mov.b64 %0, {%1, %1};" : "=l"(r) : "r"(__float_as_uint(f)));
    return r;
}
__device__ __forceinline__ void fma2(unsigned long long& d,
                                     unsigned long long a, unsigned long long b) {
    asm("fma.rn.f32x2 %0, %1, %2, %0;" : "+l"(d) : "l"(a), "l"(b));
}
__device__ __forceinline__ float2 unpack2(unsigned long long v) {
    unsigned lo, hi;
    asm("mov.b64 {%0, %1}, %2;" : "=r"(lo), "=r"(hi) : "l"(v));
    return make_float2(__uint_as_float(lo), __uint_as_float(hi));
}

// ============================================================
// init kernel: reset grid barrier (runs each graph replay)
// ============================================================
__global__ void init_bar_kernel() { g_bar = 0u; }

// ============================================================
// Kernel 1: xproj = features @ Wi^T + bi   (M=24576, N=1104, K=368)
// BM=128 BN=64 BK=16, 256 threads, thread tile 8x4, FFMA2 inner loop
// ============================================================
__global__ void xproj_kernel(const float* __restrict__ A,
                             const float* __restrict__ W,
                             const float* __restrict__ bi)
{
    __shared__ float As[16][128];
    __shared__ float Bs[16][64];

    const int m0 = blockIdx.y * 128;
    const int n0 = blockIdx.x * 64;
    const int tid = threadIdx.x;
    const int tx = tid & 15;
    const int ty = tid >> 4;

    unsigned long long accp[8][2];
#pragma unroll
    for (int i = 0; i < 8; i++) { accp[i][0] = 0ull; accp[i][1] = 0ull; }

    for (int k0 = 0; k0 < F_DIM; k0 += 16) {
#pragma unroll
        for (int l = 0; l < 2; l++) {
            int idx = tid + l * 256;
            int row = idx >> 2, kq = idx & 3;
            float4 v = *(const float4*)(A + (size_t)(m0 + row) * F_DIM + k0 + kq * 4);
            As[kq * 4 + 0][row] = v.x;
            As[kq * 4 + 1][row] = v.y;
            As[kq * 4 + 2][row] = v.z;
            As[kq * 4 + 3][row] = v.w;
        }
        {
            int row = tid >> 2, kq = tid & 3;
            int n = n0 + row;
            float4 v = make_float4(0.f, 0.f, 0.f, 0.f);
            if (n < G3)
                v = *(const float4*)(W + (size_t)n * F_DIM + k0 + kq * 4);
            Bs[kq * 4 + 0][row] = v.x;
            Bs[kq * 4 + 1][row] = v.y;
            Bs[kq * 4 + 2][row] = v.z;
            Bs[kq * 4 + 3][row] = v.w;
        }
        __syncthreads();
#pragma unroll
        for (int k = 0; k < 16; k++) {
            ulonglong2 bq = *(const ulonglong2*)&Bs[k][tx * 4];
#pragma unroll
            for (int i = 0; i < 8; i++) {
                unsigned long long ap = dup_f32(As[k][ty * 8 + i]);
                fma2(accp[i][0], ap, bq.x);
                fma2(accp[i][1], ap, bq.y);
            }
        }
        __syncthreads();
    }

    float bv[4];
#pragma unroll
    for (int j = 0; j < 4; j++) {
        int n = n0 + tx * 4 + j;
        bv[j] = (n < G3) ? bi[n] : 0.f;
    }
#pragma unroll
    for (int i = 0; i < 8; i++) {
        int m = m0 + ty * 8 + i;
        float2 p0 = unpack2(accp[i][0]);
        float2 p1 = unpack2(accp[i][1]);
        float av[4] = {p0.x, p0.y, p1.x, p1.y};
#pragma unroll
        for (int j = 0; j < 4; j++) {
            int n = n0 + tx * 4 + j;
            if (n < G3) g_xproj[(size_t)m * G3 + n] = av[j] + bv[j];
        }
    }
}

// ============================================================
// Kernel 1b: transpose xproj (b,t,g,u) -> xprojT [t][u][g][b]
// ============================================================
__global__ void xprojT_kernel()
{
    __shared__ float tile[32][33];
    const int t = blockIdx.x;
    const int u0 = blockIdx.y * 32;
    const int b0 = blockIdx.z * 32;
    const int tx = threadIdx.x, ty = threadIdx.y;

    for (int g = 0; g < 3; g++) {
        for (int bb = ty; bb < 32; bb += 8) {
            int u = u0 + tx;
            float v = 0.f;
            if (u < D_MODEL)
                v = g_xproj[((size_t)(b0 + bb) * T_SZ + t) * G3 + g * D_MODEL + u];
            tile[tx][bb] = v;
        }
        __syncthreads();
        for (int ur = ty; ur < 32; ur += 8) {
            int u = u0 + ur;
            if (u < D_MODEL)
                g_xprojT[(((size_t)t * D_MODEL + u) * 3 + g) * B_SZ + b0 + tx] = tile[ur][tx];
        }
        __syncthreads();
    }
}

// ============================================================
// Kernel 2: PERSISTENT GRU — all 96 steps in one launch.
// grid = 128 = 32 unit-groups(12 units = 36 gate-rows) x 4 batch-groups(64)
// 256 threads: tid = kq*64 + rg*16 + bg
// inner loop per k: 18 FFMA2 (36 FMA), 9 broadcast w-LDS + 9 dup + 1 LDS.128 h.
// Wh staged in smem ONCE; h exchanged via L2 (__ldcg) + grid barrier per step.
// smem: wh_s[36][368] + h_s[368][68] + red_s[3*64*36]
// ============================================================
#define HS_STRIDE 68
#define WH_FLOATS (36 * 368)
#define HSM_FLOATS (D_MODEL * HS_STRIDE)
#define RED_FLOATS (3 * 64 * 36)
#define GRU_SMEM ((WH_FLOATS + HSM_FLOATS + RED_FLOATS) * 4)

__global__ __launch_bounds__(256, 1)
void gru_persistent_kernel(const float* __restrict__ Wh,
                           const float* __restrict__ bh)
{
    extern __shared__ float sm[];
    float* wh_s  = sm;                          // [36][368]
    float* h_s   = sm + WH_FLOATS;              // [368][68]
    float* red_s = sm + WH_FLOATS + HSM_FLOATS; // [192][36]

    const int tid = threadIdx.x;
    const int ug = blockIdx.x >> 2;        // 0..31
    const int bgi = blockIdx.x & 3;        // 0..3
    const int b0 = bgi * 64;
    const int u_base = ug * 12;

    const int kq = tid >> 6;               // 0..3
    const int rg = (tid >> 4) & 3;         // 0..3
    const int bg = tid & 15;               // 0..15
    const int t2 = rg * 16 + bg;           // 0..63

    // ---- stage Wh slice ONCE: rows r = ul*3+g (ul 0..11), zero-pad u>=368 ----
    for (int idx = tid; idx < 36 * 92; idx += 256) {
        int r = idx / 92, q = idx - r * 92;
        int ul = r / 3, g = r - ul * 3;
        int u = u_base + ul;
        float4 v = make_float4(0.f, 0.f, 0.f, 0.f);
        if (u < D_MODEL)
            v = *(const float4*)(Wh + ((size_t)(g * D_MODEL + u)) * D_MODEL + q * 4);
        *(float4*)(wh_s + r * 368 + q * 4) = v;
    }

    // bias for this thread's 3 units (constant across steps)
    float bhr[3], bhz[3], bhn[3];
#pragma unroll
    for (int ul3 = 0; ul3 < 3; ul3++) {
        int d = u_base + rg * 3 + ul3;
        int dd = (d < D_MODEL) ? d : 0;
        bhr[ul3] = bh[dd];
        bhz[ul3] = bh[D_MODEL + dd];
        bhn[ul3] = bh[2 * D_MODEL + dd];
    }

    for (int t = 0; t < T_SZ; t++) {
        // ---- fill h_s with h_{t-1} (L2-coherent loads) ----
        if (t > 0) {
            const float* hp = g_h + (size_t)(t - 1) * D_MODEL * B_SZ;
#pragma unroll 4
            for (int idx = tid; idx < D_MODEL * 16; idx += 256) {
                int u = idx >> 4, c = idx & 15;
                float4 v = __ldcg((const float4*)(hp + (size_t)u * B_SZ + b0 + c * 4));
                *(float4*)(h_s + u * HS_STRIDE + c * 4) = v;
            }
        }
        __syncthreads();

        // ---- partial GEMM (FFMA2) ----
        unsigned long long acc2[9][2];
#pragma unroll
        for (int j = 0; j < 9; j++) { acc2[j][0] = 0ull; acc2[j][1] = 0ull; }

        if (t > 0) {
            const float* wp = wh_s + (rg * 9) * 368 + kq * 92;
            const float* hp2 = h_s + (kq * 92) * HS_STRIDE + bg * 4;
#pragma unroll 2
            for (int k = 0; k < 92; k++) {
                ulonglong2 hv = *(const ulonglong2*)(hp2 + (size_t)k * HS_STRIDE);
#pragma unroll
                for (int j = 0; j < 9; j++) {
                    unsigned long long wpair = dup_f32(wp[j * 368 + k]);
                    fma2(acc2[j][0], hv.x, wpair);
                    fma2(acc2[j][1], hv.y, wpair);
                }
            }
        }

        // ---- kq-partial reduction through red_s ----
        __syncthreads();
        if (kq > 0) {
            float* dst = red_s + ((kq - 1) * 64 + t2) * 36;
#pragma unroll
            for (int j = 0; j < 9; j++)
                *(ulonglong2*)(dst + j * 4) = make_ulonglong2(acc2[j][0], acc2[j][1]);
        }
        __syncthreads();

        if (kq == 0) {
            float acc[9][4];
#pragma unroll
            for (int j = 0; j < 9; j++) {
                float2 p0 = unpack2(acc2[j][0]);
                float2 p1 = unpack2(acc2[j][1]);
                acc[j][0] = p0.x; acc[j][1] = p0.y; acc[j][2] = p1.x; acc[j][3] = p1.y;
            }
#pragma unroll
            for (int q = 0; q < 3; q++) {
                const float* src = red_s + (q * 64 + t2) * 36;
#pragma unroll
                for (int j = 0; j < 9; j++) {
                    float4 v = *(const float4*)(src + j * 4);
                    acc[j][0] += v.x; acc[j][1] += v.y; acc[j][2] += v.z; acc[j][3] += v.w;
                }
            }

            // ---- gate math for 3 units x 4 batches ----
            const float* xT = g_xprojT + (size_t)t * D_MODEL * 3 * B_SZ;
            float* hout = g_h + (size_t)t * D_MODEL * B_SZ;
#pragma unroll
            for (int ul3 = 0; ul3 < 3; ul3++) {
                int d = u_base + rg * 3 + ul3;
                if (d < D_MODEL) {
                    float4 gr = __ldg((const float4*)(xT + ((size_t)d * 3 + 0) * B_SZ + b0 + bg * 4));
                    float4 gz = __ldg((const float4*)(xT + ((size_t)d * 3 + 1) * B_SZ + b0 + bg * 4));
                    float4 gn = __ldg((const float4*)(xT + ((size_t)d * 3 + 2) * B_SZ + b0 + bg * 4));
                    float girv[4] = {gr.x, gr.y, gr.z, gr.w};
                    float gizv[4] = {gz.x, gz.y, gz.z, gz.w};
                    float ginv[4] = {gn.x, gn.y, gn.z, gn.w};
                    float res[4];
#pragma unroll
                    for (int c = 0; c < 4; c++) {
                        float ghr = acc[ul3 * 3 + 0][c] + bhr[ul3];
                        float ghz = acc[ul3 * 3 + 1][c] + bhz[ul3];
                        float ghn = acc[ul3 * 3 + 2][c] + bhn[ul3];
                        float rr = 1.f / (1.f + expf(-(girv[c] + ghr)));
                        float zz = 1.f / (1.f + expf(-(gizv[c] + ghz)));
                        float nn = tanhf(ginv[c] + rr * ghn);
                        float hprev = (t > 0) ? h_s[d * HS_STRIDE + bg * 4 + c] : 0.f;
                        res[c] = (1.f - zz) * nn + zz * hprev;
                    }
                    *(float4*)(hout + (size_t)d * B_SZ + b0 + bg * 4) =
                        make_float4(res[0], res[1], res[2], res[3]);
                }
            }
        }

        // ---- grid barrier (skip after last step) ----
        __syncthreads();
        if (t < T_SZ - 1) {
            if (tid == 0) {
                __threadfence();                 // release: publish h[t]
                atomicAdd(&g_bar, 1u);
                unsigned target = 128u * (unsigned)(t + 1);
                while (*(volatile unsigned*)&g_bar < target) { }
                __threadfence();                 // acquire
            }
            __syncthreads();
        }
    }
}

// ============================================================
// Kernel 2b: transpose g_h [t][d][b] -> g_temporal (b,t,d)
// ============================================================
__global__ void hT_kernel()
{
    __shared__ float tile[32][33];
    const int t = blockIdx.x;
    const int d0 = blockIdx.y * 32;
    const int b0 = blockIdx.z * 32;
    const int tx = threadIdx.x, ty = threadIdx.y;

    for (int dr = ty; dr < 32; dr += 8) {
        int d = d0 + dr;
        float v = 0.f;
        if (d < D_MODEL)
            v = g_h[((size_t)t * D_MODEL + d) * B_SZ + b0 + tx];
        tile[dr][tx] = v;
    }
    __syncthreads();
    for (int br = ty; br < 32; br += 8) {
        int d = d0 + tx;
        if (d < D_MODEL)
            g_temporal[((size_t)(b0 + br) * T_SZ + t) * D_MODEL + d] = tile[tx][br];
    }
}

// ============================================================
// Kernel 3: logits = temporal @ [Wc;Wf]^T + [bc;bf]
// ============================================================
#define HEAD_SMEM ((31 * 368 + 256 * 93) * 4)

__global__ void head_kernel(const float* __restrict__ Wc,
                            const float* __restrict__ bc,
                            const float* __restrict__ Wf,
                            const float* __restrict__ bf)
{
    extern __shared__ float sm[];
    float* W_s = sm;               // [31][368]
    float* A_s = sm + 31 * 368;    // [256][93]

    const int m0 = blockIdx.x * 256;
    const int tid = threadIdx.x;

    for (int idx = tid; idx < 31 * 92; idx += 128) {
        int row = idx / 92, kq = idx % 92;
        const float* src = (row < 2) ? (Wc + (size_t)row * D_MODEL)
                                     : (Wf + (size_t)(row - 2) * D_MODEL);
        float4 v = *(const float4*)(src + kq * 4);
        *(float4*)(W_s + row * D_MODEL + kq * 4) = v;
    }

    float acc0[NOUT], acc1[NOUT];
#pragma unroll
    for (int o = 0; o < NOUT; o++) { acc0[o] = 0.f; acc1[o] = 0.f; }

    for (int c = 0; c < 4; c++) {
        __syncthreads();
        for (int idx = tid; idx < 256 * 23; idx += 128) {
            int row = idx / 23, kq = idx % 23;
            float4 v = *(const float4*)(g_temporal +
                         (size_t)(m0 + row) * D_MODEL + c * 92 + kq * 4);
            float* dst = A_s + row * 93 + kq * 4;
            dst[0] = v.x; dst[1] = v.y; dst[2] = v.z; dst[3] = v.w;
        }
        __syncthreads();
#pragma unroll 4
        for (int k = 0; k < 92; k++) {
            float a0 = A_s[tid * 93 + k];
            float a1 = A_s[(tid + 128) * 93 + k];
#pragma unroll
            for (int o = 0; o < NOUT; o++) {
                float w = W_s[o * D_MODEL + c * 92 + k];
                acc0[o] += a0 * w;
                acc1[o] += a1 * w;
            }
        }
    }

#pragma unroll
    for (int o = 0; o < NOUT; o++) {
        float bias = (o < 2) ? bc[o] : bf[o - 2];
        g_logits[(size_t)(m0 + tid) * NOUT + o] = acc0[o] + bias;
        g_logits[(size_t)(m0 + tid + 128) * NOUT + o] = acc1[o] + bias;
    }
}

// ============================================================
// Kernel 4: softmax + sigmoid + NMS + argmax
// ============================================================
__global__ void finalize_kernel(float* __restrict__ out)
{
    __shared__ float bg_s[T_SZ];
    const int b = blockIdx.x;
    const int t = threadIdx.x;
    const size_t mi = (size_t)b * T_SZ + t;
    const float* L = g_logits + mi * NOUT;

    float l0 = L[0], l1 = L[1];
    float mx = fmaxf(l0, l1);
    float e0 = expf(l0 - mx), e1 = expf(l1 - mx);
    float inv = 1.f / (e0 + e1);
    float s0 = e0 * inv, s1 = e1 * inv;
    bg_s[t] = s0;

#pragma unroll
    for (int j = 0; j < NCLS; j++) {
        float v = 1.f / (1.f + expf(-L[2 + j]));
        out[(size_t)M_ROWS * 3 + mi * NCLS + j] = v;
    }
    __syncthreads();

    float wmin = s0;
#pragma unroll
    for (int dt = -2; dt <= 2; dt++) {
        int tt = t + dt;
        if (tt >= 0 && tt < T_SZ) wmin = fminf(wmin, bg_s[tt]);
    }
    bool keep = (s0 == wmin);
    float n0 = keep ? s0 : 0.f;
    float n1 = keep ? s1 : 0.f;

    out[mi] = (n1 > n0) ? 1.f : 0.f;
    out[M_ROWS + mi * 2 + 0] = n0;
    out[M_ROWS + mi * 2 + 1] = n1;
}

// ============================================================
extern "C" void kernel_launch(void* const* d_in, const int* in_sizes, int n_in,
                              void* d_out, int out_size)
{
    const float* features = (const float*)d_in[0];
    // d_in[1] = hand (unused)
    const float* Wi = (const float*)d_in[2];
    const float* Wh = (const float*)d_in[3];
    const float* bi = (const float*)d_in[4];
    const float* bh = (const float*)d_in[5];
    const float* Wc = (const float*)d_in[6];
    const float* bc = (const float*)d_in[7];
    const float* Wf = (const float*)d_in[8];
    const float* bf = (const float*)d_in[9];
    float* out = (float*)d_out;

    cudaFuncSetAttribute(gru_persistent_kernel,
                         cudaFuncAttributeMaxDynamicSharedMemorySize, GRU_SMEM);
    cudaFuncSetAttribute(head_kernel,
                         cudaFuncAttributeMaxDynamicSharedMemorySize, HEAD_SMEM);

    // 0) reset grid barrier
    init_bar_kernel<<<1, 1>>>();

    // 1) input projection + transpose to [t][u][g][b]
    dim3 xg((G3 + 63) / 64, M_ROWS / 128);
    xproj_kernel<<<xg, 256>>>(features, Wi, bi);
    xprojT_kernel<<<dim3(T_SZ, 12, 8), dim3(32, 8)>>>();

    // 2) recurrence: ONE persistent launch for all 96 steps
    gru_persistent_kernel<<<128, 256, GRU_SMEM>>>(Wh, bh);

    // 2b) transpose hidden states to (b,t,d) for heads
    hT_kernel<<<dim3(T_SZ, 12, 8), dim3(32, 8)>>>();

    // 3) output heads
    head_kernel<<<M_ROWS / 256, 128, HEAD_SMEM>>>(Wc, bc, Wf, bf);

    // 4) softmax/sigmoid/NMS/argmax
    finalize_kernel<<<B_SZ, T_SZ>>>(out);
}

// round 6
// speedup vs baseline: 1.4613x; 1.1053x over previous
#include <cuda_runtime.h>
#include <math.h>

// Problem constants
#define B_SZ 256
#define T_SZ 96
#define F_DIM 368
#define D_MODEL 368
#define G3 1104          // 3*D_MODEL
#define NCLS 29
#define NOUT 31          // 2 coarse + 29 fine
#define M_ROWS 24576     // B*T

// -------- device scratch (static __device__ arrays; no allocation) --------
__device__ float g_xproj[(size_t)M_ROWS * G3];                 // (B*T, 3D)
__device__ float g_xprojT[(size_t)T_SZ * D_MODEL * 3 * B_SZ];  // [t][u][g][b]
__device__ float g_h[(size_t)T_SZ * D_MODEL * B_SZ];           // [t][d][b]
__device__ float g_temporal[(size_t)M_ROWS * D_MODEL];         // (B,T,D)
__device__ float g_logits[(size_t)M_ROWS * NOUT];
__device__ unsigned g_bar;                                     // grid barrier counter

// -------- packed f32x2 helpers (Blackwell FFMA2) --------
__device__ __forceinline__ unsigned long long dup_f32(float f) {
    unsigned long long r;
    asm("mov.b64 %0, {%1, %1};" : "=l"(r) : "r"(__float_as_uint(f)));
    return r;
}
__device__ __forceinline__ void fma2(unsigned long long& d,
                                     unsigned long long a, unsigned long long b) {
    asm("fma.rn.f32x2 %0, %1, %2, %0;" : "+l"(d) : "l"(a), "l"(b));
}
__device__ __forceinline__ float2 unpack2(unsigned long long v) {
    unsigned lo, hi;
    asm("mov.b64 {%0, %1}, %2;" : "=r"(lo), "=r"(hi) : "l"(v));
    return make_float2(__uint_as_float(lo), __uint_as_float(hi));
}

__device__ __forceinline__ float fast_sigmoid(float x) {
    return __fdividef(1.f, 1.f + expf(-x));
}
__device__ __forceinline__ float fast_tanh(float x) {
    return __fdividef(2.f, 1.f + expf(-2.f * x)) - 1.f;
}

// ============================================================
// init kernel: reset grid barrier (runs each graph replay)
// ============================================================
__global__ void init_bar_kernel() { g_bar = 0u; }

// ============================================================
// Kernel 1: xproj = features @ Wi^T + bi   (M=24576, N=1104, K=368)
// BM=128 BN=64 BK=16, 256 threads, thread tile 8x4, FFMA2 inner loop
// ============================================================
__global__ void xproj_kernel(const float* __restrict__ A,
                             const float* __restrict__ W,
                             const float* __restrict__ bi)
{
    __shared__ float As[16][128];
    __shared__ float Bs[16][64];

    const int m0 = blockIdx.y * 128;
    const int n0 = blockIdx.x * 64;
    const int tid = threadIdx.x;
    const int tx = tid & 15;
    const int ty = tid >> 4;

    unsigned long long accp[8][2];
#pragma unroll
    for (int i = 0; i < 8; i++) { accp[i][0] = 0ull; accp[i][1] = 0ull; }

    for (int k0 = 0; k0 < F_DIM; k0 += 16) {
#pragma unroll
        for (int l = 0; l < 2; l++) {
            int idx = tid + l * 256;
            int row = idx >> 2, kq = idx & 3;
            float4 v = *(const float4*)(A + (size_t)(m0 + row) * F_DIM + k0 + kq * 4);
            As[kq * 4 + 0][row] = v.x;
            As[kq * 4 + 1][row] = v.y;
            As[kq * 4 + 2][row] = v.z;
            As[kq * 4 + 3][row] = v.w;
        }
        {
            int row = tid >> 2, kq = tid & 3;
            int n = n0 + row;
            float4 v = make_float4(0.f, 0.f, 0.f, 0.f);
            if (n < G3)
                v = *(const float4*)(W + (size_t)n * F_DIM + k0 + kq * 4);
            Bs[kq * 4 + 0][row] = v.x;
            Bs[kq * 4 + 1][row] = v.y;
            Bs[kq * 4 + 2][row] = v.z;
            Bs[kq * 4 + 3][row] = v.w;
        }
        __syncthreads();
#pragma unroll
        for (int k = 0; k < 16; k++) {
            ulonglong2 bq = *(const ulonglong2*)&Bs[k][tx * 4];
#pragma unroll
            for (int i = 0; i < 8; i++) {
                unsigned long long ap = dup_f32(As[k][ty * 8 + i]);
                fma2(accp[i][0], ap, bq.x);
                fma2(accp[i][1], ap, bq.y);
            }
        }
        __syncthreads();
    }

    float bv[4];
#pragma unroll
    for (int j = 0; j < 4; j++) {
        int n = n0 + tx * 4 + j;
        bv[j] = (n < G3) ? bi[n] : 0.f;
    }
#pragma unroll
    for (int i = 0; i < 8; i++) {
        int m = m0 + ty * 8 + i;
        float2 p0 = unpack2(accp[i][0]);
        float2 p1 = unpack2(accp[i][1]);
        float av[4] = {p0.x, p0.y, p1.x, p1.y};
#pragma unroll
        for (int j = 0; j < 4; j++) {
            int n = n0 + tx * 4 + j;
            if (n < G3) g_xproj[(size_t)m * G3 + n] = av[j] + bv[j];
        }
    }
}

// ============================================================
// Kernel 1b: transpose xproj (b,t,g,u) -> xprojT [t][u][g][b]
// ============================================================
__global__ void xprojT_kernel()
{
    __shared__ float tile[32][33];
    const int t = blockIdx.x;
    const int u0 = blockIdx.y * 32;
    const int b0 = blockIdx.z * 32;
    const int tx = threadIdx.x, ty = threadIdx.y;

    for (int g = 0; g < 3; g++) {
        for (int bb = ty; bb < 32; bb += 8) {
            int u = u0 + tx;
            float v = 0.f;
            if (u < D_MODEL)
                v = g_xproj[((size_t)(b0 + bb) * T_SZ + t) * G3 + g * D_MODEL + u];
            tile[tx][bb] = v;
        }
        __syncthreads();
        for (int ur = ty; ur < 32; ur += 8) {
            int u = u0 + ur;
            if (u < D_MODEL)
                g_xprojT[(((size_t)t * D_MODEL + u) * 3 + g) * B_SZ + b0 + tx] = tile[ur][tx];
        }
        __syncthreads();
    }
}

// ============================================================
// Kernel 2: PERSISTENT GRU — all 96 steps in one launch.
// grid = 128 = 16 unit-groups(23 units = 69 rows, pad 72) x 8 batch-groups(32)
// 128 threads: tid = kq*32 + rg*4 + bg  (warp = kq; 1 warp/SMSP)
// thread tile: 9 rows x 8 batches -> 36 FFMA2 per k, 11 LDS per k.
// Wh staged once (stride 388: conflict-free rg-spread).
// h exchange via L2 (6 MB/step) + grid barrier.
// Epilogue parallel across all 4 warps (partials via smem).
// smem: wh_s[72][388] + h_s[368][36] + red_s[4][72*36]
// ============================================================
#define WST 388
#define HST 36
#define WH_FLOATS (72 * WST)
#define HSM_FLOATS (D_MODEL * HST)
#define RED_STRIDE (72 * 36)
#define RED_FLOATS (4 * RED_STRIDE)
#define GRU_SMEM ((WH_FLOATS + HSM_FLOATS + RED_FLOATS) * 4)

__global__ __launch_bounds__(128, 1)
void gru_persistent_kernel(const float* __restrict__ Wh,
                           const float* __restrict__ bh)
{
    extern __shared__ float sm[];
    float* wh_s  = sm;                          // [72][388]
    float* h_s   = sm + WH_FLOATS;              // [368][36]
    float* red_s = sm + WH_FLOATS + HSM_FLOATS; // [4][72*36]

    const int tid = threadIdx.x;
    const int ug  = blockIdx.x >> 3;       // 0..15
    const int bgi = blockIdx.x & 7;        // 0..7
    const int b0 = bgi * 32;
    const int u_base = ug * 23;

    const int kq = tid >> 5;               // 0..3 (warp id)
    const int lane = tid & 31;
    const int rg = lane >> 2;              // 0..7
    const int bg = lane & 3;               // 0..3

    // ---- stage Wh slice ONCE: rows r = ul*3+g (ul 0..22 real, 23 pad) ----
    for (int idx = tid; idx < 72 * 92; idx += 128) {
        int r = idx / 92, q = idx - r * 92;
        int ul = r / 3, g = r - ul * 3;
        float4 v = make_float4(0.f, 0.f, 0.f, 0.f);
        if (ul < 23)
            v = *(const float4*)(Wh + ((size_t)(g * D_MODEL + u_base + ul)) * D_MODEL + q * 4);
        *(float4*)(wh_s + r * WST + q * 4) = v;
    }

    for (int t = 0; t < T_SZ; t++) {
        // ---- fill h_s with h_{t-1}[all 368 units][our 32 batches] ----
        if (t > 0) {
            const float* hp = g_h + (size_t)(t - 1) * D_MODEL * B_SZ;
#pragma unroll 4
            for (int idx = tid; idx < D_MODEL * 8; idx += 128) {
                int u = idx >> 3, c = idx & 7;
                float4 v = __ldcg((const float4*)(hp + (size_t)u * B_SZ + b0 + c * 4));
                *(float4*)(h_s + u * HST + c * 4) = v;
            }
        }
        __syncthreads();

        // ---- partial GEMM: 9 rows x 8 batches (4 f32x2 pairs) ----
        unsigned long long acc2[9][4];
#pragma unroll
        for (int j = 0; j < 9; j++)
#pragma unroll
            for (int p = 0; p < 4; p++) acc2[j][p] = 0ull;

        if (t > 0) {
            const float* wp = wh_s + (rg * 9) * WST + kq * 92;
            const float* hp2 = h_s + (kq * 92) * HST + bg * 8;
#pragma unroll 4
            for (int k = 0; k < 92; k++) {
                ulonglong2 hv0 = *(const ulonglong2*)(hp2 + k * HST);
                ulonglong2 hv1 = *(const ulonglong2*)(hp2 + k * HST + 4);
#pragma unroll
                for (int j = 0; j < 9; j++) {
                    unsigned long long wd = dup_f32(wp[j * WST + k]);
                    fma2(acc2[j][0], hv0.x, wd);
                    fma2(acc2[j][1], hv0.y, wd);
                    fma2(acc2[j][2], hv1.x, wd);
                    fma2(acc2[j][3], hv1.y, wd);
                }
            }
        }

        // ---- all kq write partials to red_s ----
        __syncthreads();   // h_s reads done before potential overlap hazards? (red_s separate; this sync orders partials)
        {
            float* dst = red_s + kq * RED_STRIDE;
#pragma unroll
            for (int j = 0; j < 9; j++) {
                int row = rg * 9 + j;
                *(ulonglong2*)(dst + row * 36 + bg * 8) =
                    make_ulonglong2(acc2[j][0], acc2[j][1]);
                *(ulonglong2*)(dst + row * 36 + bg * 8 + 4) =
                    make_ulonglong2(acc2[j][2], acc2[j][3]);
            }
        }
        __syncthreads();

        // ---- parallel epilogue: each thread 6 outputs (unit, batch) ----
        const float* xT = g_xprojT + (size_t)t * D_MODEL * 3 * B_SZ;
        float* hout = g_h + (size_t)t * D_MODEL * B_SZ;
#pragma unroll
        for (int i = 0; i < 6; i++) {
            int o = tid + i * 128;        // 0..767
            int ul = o >> 5;              // 0..23 (23 = pad)
            int b  = o & 31;
            if (ul < 23) {
                int d = u_base + ul;
                float gsum[3];
#pragma unroll
                for (int g = 0; g < 3; g++) {
                    int row = ul * 3 + g;
                    float s = red_s[0 * RED_STRIDE + row * 36 + b]
                            + red_s[1 * RED_STRIDE + row * 36 + b]
                            + red_s[2 * RED_STRIDE + row * 36 + b]
                            + red_s[3 * RED_STRIDE + row * 36 + b];
                    gsum[g] = s;
                }
                float ghr = gsum[0] + __ldg(bh + d);
                float ghz = gsum[1] + __ldg(bh + D_MODEL + d);
                float ghn = gsum[2] + __ldg(bh + 2 * D_MODEL + d);
                float gir = __ldg(xT + ((size_t)d * 3 + 0) * B_SZ + b0 + b);
                float giz = __ldg(xT + ((size_t)d * 3 + 1) * B_SZ + b0 + b);
                float gin = __ldg(xT + ((size_t)d * 3 + 2) * B_SZ + b0 + b);
                float rr = fast_sigmoid(gir + ghr);
                float zz = fast_sigmoid(giz + ghz);
                float nn = fast_tanh(gin + rr * ghn);
                float hprev = (t > 0) ? h_s[d * HST + b] : 0.f;
                hout[(size_t)d * B_SZ + b0 + b] = (1.f - zz) * nn + zz * hprev;
            }
        }

        // ---- grid barrier (skip after last step) ----
        __syncthreads();
        if (t < T_SZ - 1) {
            if (tid == 0) {
                __threadfence();                 // release: publish h[t]
                atomicAdd(&g_bar, 1u);
                unsigned target = 128u * (unsigned)(t + 1);
                while (*(volatile unsigned*)&g_bar < target) { }
                __threadfence();                 // acquire
            }
            __syncthreads();
        }
    }
}

// ============================================================
// Kernel 2b: transpose g_h [t][d][b] -> g_temporal (b,t,d)
// ============================================================
__global__ void hT_kernel()
{
    __shared__ float tile[32][33];
    const int t = blockIdx.x;
    const int d0 = blockIdx.y * 32;
    const int b0 = blockIdx.z * 32;
    const int tx = threadIdx.x, ty = threadIdx.y;

    for (int dr = ty; dr < 32; dr += 8) {
        int d = d0 + dr;
        float v = 0.f;
        if (d < D_MODEL)
            v = g_h[((size_t)t * D_MODEL + d) * B_SZ + b0 + tx];
        tile[dr][tx] = v;
    }
    __syncthreads();
    for (int br = ty; br < 32; br += 8) {
        int d = d0 + tx;
        if (d < D_MODEL)
            g_temporal[((size_t)(b0 + br) * T_SZ + t) * D_MODEL + d] = tile[tx][br];
    }
}

// ============================================================
// Kernel 3: logits = temporal @ [Wc;Wf]^T + [bc;bf]
// ============================================================
#define HEAD_SMEM ((31 * 368 + 256 * 93) * 4)

__global__ void head_kernel(const float* __restrict__ Wc,
                            const float* __restrict__ bc,
                            const float* __restrict__ Wf,
                            const float* __restrict__ bf)
{
    extern __shared__ float sm[];
    float* W_s = sm;               // [31][368]
    float* A_s = sm + 31 * 368;    // [256][93]

    const int m0 = blockIdx.x * 256;
    const int tid = threadIdx.x;

    for (int idx = tid; idx < 31 * 92; idx += 128) {
        int row = idx / 92, kq = idx % 92;
        const float* src = (row < 2) ? (Wc + (size_t)row * D_MODEL)
                                     : (Wf + (size_t)(row - 2) * D_MODEL);
        float4 v = *(const float4*)(src + kq * 4);
        *(float4*)(W_s + row * D_MODEL + kq * 4) = v;
    }

    float acc0[NOUT], acc1[NOUT];
#pragma unroll
    for (int o = 0; o < NOUT; o++) { acc0[o] = 0.f; acc1[o] = 0.f; }

    for (int c = 0; c < 4; c++) {
        __syncthreads();
        for (int idx = tid; idx < 256 * 23; idx += 128) {
            int row = idx / 23, kq = idx % 23;
            float4 v = *(const float4*)(g_temporal +
                         (size_t)(m0 + row) * D_MODEL + c * 92 + kq * 4);
            float* dst = A_s + row * 93 + kq * 4;
            dst[0] = v.x; dst[1] = v.y; dst[2] = v.z; dst[3] = v.w;
        }
        __syncthreads();
#pragma unroll 4
        for (int k = 0; k < 92; k++) {
            float a0 = A_s[tid * 93 + k];
            float a1 = A_s[(tid + 128) * 93 + k];
#pragma unroll
            for (int o = 0; o < NOUT; o++) {
                float w = W_s[o * D_MODEL + c * 92 + k];
                acc0[o] += a0 * w;
                acc1[o] += a1 * w;
            }
        }
    }

#pragma unroll
    for (int o = 0; o < NOUT; o++) {
        float bias = (o < 2) ? bc[o] : bf[o - 2];
        g_logits[(size_t)(m0 + tid) * NOUT + o] = acc0[o] + bias;
        g_logits[(size_t)(m0 + tid + 128) * NOUT + o] = acc1[o] + bias;
    }
}

// ============================================================
// Kernel 4: softmax + sigmoid + NMS + argmax
// ============================================================
__global__ void finalize_kernel(float* __restrict__ out)
{
    __shared__ float bg_s[T_SZ];
    const int b = blockIdx.x;
    const int t = threadIdx.x;
    const size_t mi = (size_t)b * T_SZ + t;
    const float* L = g_logits + mi * NOUT;

    float l0 = L[0], l1 = L[1];
    float mx = fmaxf(l0, l1);
    float e0 = expf(l0 - mx), e1 = expf(l1 - mx);
    float inv = 1.f / (e0 + e1);
    float s0 = e0 * inv, s1 = e1 * inv;
    bg_s[t] = s0;

#pragma unroll
    for (int j = 0; j < NCLS; j++) {
        float v = 1.f / (1.f + expf(-L[2 + j]));
        out[(size_t)M_ROWS * 3 + mi * NCLS + j] = v;
    }
    __syncthreads();

    float wmin = s0;
#pragma unroll
    for (int dt = -2; dt <= 2; dt++) {
        int tt = t + dt;
        if (tt >= 0 && tt < T_SZ) wmin = fminf(wmin, bg_s[tt]);
    }
    bool keep = (s0 == wmin);
    float n0 = keep ? s0 : 0.f;
    float n1 = keep ? s1 : 0.f;

    out[mi] = (n1 > n0) ? 1.f : 0.f;
    out[M_ROWS + mi * 2 + 0] = n0;
    out[M_ROWS + mi * 2 + 1] = n1;
}

// ============================================================
extern "C" void kernel_launch(void* const* d_in, const int* in_sizes, int n_in,
                              void* d_out, int out_size)
{
    const float* features = (const float*)d_in[0];
    // d_in[1] = hand (unused)
    const float* Wi = (const float*)d_in[2];
    const float* Wh = (const float*)d_in[3];
    const float* bi = (const float*)d_in[4];
    const float* bh = (const float*)d_in[5];
    const float* Wc = (const float*)d_in[6];
    const float* bc = (const float*)d_in[7];
    const float* Wf = (const float*)d_in[8];
    const float* bf = (const float*)d_in[9];
    float* out = (float*)d_out;

    cudaFuncSetAttribute(gru_persistent_kernel,
                         cudaFuncAttributeMaxDynamicSharedMemorySize, GRU_SMEM);
    cudaFuncSetAttribute(head_kernel,
                         cudaFuncAttributeMaxDynamicSharedMemorySize, HEAD_SMEM);

    // 0) reset grid barrier
    init_bar_kernel<<<1, 1>>>();

    // 1) input projection + transpose to [t][u][g][b]
    dim3 xg((G3 + 63) / 64, M_ROWS / 128);
    xproj_kernel<<<xg, 256>>>(features, Wi, bi);
    xprojT_kernel<<<dim3(T_SZ, 12, 8), dim3(32, 8)>>>();

    // 2) recurrence: ONE persistent launch for all 96 steps
    gru_persistent_kernel<<<128, 128, GRU_SMEM>>>(Wh, bh);

    // 2b) transpose hidden states to (b,t,d) for heads
    hT_kernel<<<dim3(T_SZ, 12, 8), dim3(32, 8)>>>();

    // 3) output heads
    head_kernel<<<M_ROWS / 256, 128, HEAD_SMEM>>>(Wc, bc, Wf, bf);

    // 4) softmax/sigmoid/NMS/argmax
    finalize_kernel<<<B_SZ, T_SZ>>>(out);
}

// round 11
// speedup vs baseline: 1.8042x; 1.2346x over previous
#include <cuda_runtime.h>
#include <math.h>

// Problem constants
#define B_SZ 256
#define T_SZ 96
#define F_DIM 368
#define D_MODEL 368
#define G3 1104          // 3*D_MODEL
#define NCLS 29
#define NOUT 31          // 2 coarse + 29 fine
#define M_ROWS 24576     // B*T

// -------- device scratch --------
__device__ float g_xprojT[(size_t)T_SZ * D_MODEL * 3 * B_SZ];  // [t][u][g][b]
__device__ float g_h[(size_t)T_SZ * D_MODEL * B_SZ];           // [t][d][b]
__device__ float g_logitsT[(size_t)T_SZ * B_SZ * NOUT];        // [t][b][o]
__device__ unsigned g_bars[8];                                 // per-batch-group barriers

// -------- packed f32x2 helpers (Blackwell FFMA2) --------
__device__ __forceinline__ unsigned long long dup_f32(float f) {
    unsigned long long r;
    asm("mov.b64 %0, {%1, %1};" : "=l"(r) : "r"(__float_as_uint(f)));
    return r;
}
__device__ __forceinline__ void fma2(unsigned long long& d,
                                     unsigned long long a, unsigned long long b) {
    asm("fma.rn.f32x2 %0, %1, %2, %0;" : "+l"(d) : "l"(a), "l"(b));
}
__device__ __forceinline__ float2 unpack2(unsigned long long v) {
    unsigned lo, hi;
    asm("mov.b64 {%0, %1}, %2;" : "=r"(lo), "=r"(hi) : "l"(v));
    return make_float2(__uint_as_float(lo), __uint_as_float(hi));
}
__device__ __forceinline__ float fast_sigmoid(float x) {
    return __fdividef(1.f, 1.f + expf(-x));
}
__device__ __forceinline__ float fast_tanh(float x) {
    return __fdividef(2.f, 1.f + expf(-2.f * x)) - 1.f;
}

// -------- cp.async helpers --------
__device__ __forceinline__ void cp16(void* smem_dst, const void* gsrc) {
    unsigned d = (unsigned)__cvta_generic_to_shared(smem_dst);
    asm volatile("cp.async.cg.shared.global [%0], [%1], 16;\n" :: "r"(d), "l"(gsrc));
}
__device__ __forceinline__ void cp_commit() {
    asm volatile("cp.async.commit_group;\n");
}
template <int N>
__device__ __forceinline__ void cp_wait() {
    asm volatile("cp.async.wait_group %0;\n" :: "n"(N));
}

// ============================================================
// init kernel: reset barriers (runs each graph replay)
// ============================================================
__global__ void init_bar_kernel() {
    for (int i = 0; i < 8; i++) g_bars[i] = 0u;
}

// ============================================================
// Kernel 1: xproj direct into [t][u][g][b] layout.
// grid (18 n-tiles, 2 b-tiles, 96 t), 256 threads, BK=16, tile 8b x 4n
// ============================================================
__global__ void xproj_kernel(const float* __restrict__ A,
                             const float* __restrict__ W,
                             const float* __restrict__ bi)
{
    __shared__ float As[16][128];
    __shared__ float Bs[16][64];

    const int t  = blockIdx.z;
    const int b0 = blockIdx.y * 128;
    const int n0 = blockIdx.x * 64;
    const int tid = threadIdx.x;
    const int tx = tid & 15;        // 4 n each
    const int ty = tid >> 4;        // 8 b each

    unsigned long long accp[8][2];
#pragma unroll
    for (int i = 0; i < 8; i++) { accp[i][0] = 0ull; accp[i][1] = 0ull; }

    for (int k0 = 0; k0 < F_DIM; k0 += 16) {
#pragma unroll
        for (int l = 0; l < 2; l++) {
            int idx = tid + l * 256;
            int row = idx >> 2, kq = idx & 3;   // row = batch lane
            float4 v = *(const float4*)(A + ((size_t)(b0 + row) * T_SZ + t) * F_DIM + k0 + kq * 4);
            As[kq * 4 + 0][row] = v.x;
            As[kq * 4 + 1][row] = v.y;
            As[kq * 4 + 2][row] = v.z;
            As[kq * 4 + 3][row] = v.w;
        }
        {
            int row = tid >> 2, kq = tid & 3;
            int n = n0 + row;
            float4 v = make_float4(0.f, 0.f, 0.f, 0.f);
            if (n < G3)
                v = *(const float4*)(W + (size_t)n * F_DIM + k0 + kq * 4);
            Bs[kq * 4 + 0][row] = v.x;
            Bs[kq * 4 + 1][row] = v.y;
            Bs[kq * 4 + 2][row] = v.z;
            Bs[kq * 4 + 3][row] = v.w;
        }
        __syncthreads();
#pragma unroll
        for (int k = 0; k < 16; k++) {
            ulonglong2 bq = *(const ulonglong2*)&Bs[k][tx * 4];
#pragma unroll
            for (int i = 0; i < 8; i++) {
                unsigned long long ap = dup_f32(As[k][ty * 8 + i]);
                fma2(accp[i][0], ap, bq.x);
                fma2(accp[i][1], ap, bq.y);
            }
        }
        __syncthreads();
    }

    // write transposed: for each n, 8 consecutive batches
#pragma unroll
    for (int j = 0; j < 4; j++) {
        int n = n0 + tx * 4 + j;
        if (n < G3) {
            int g = n / D_MODEL, u = n - g * D_MODEL;
            float bv = bi[n];
            float col[8];
#pragma unroll
            for (int i = 0; i < 8; i++) {
                float2 p = unpack2(accp[i][j >> 1]);
                col[i] = ((j & 1) ? p.y : p.x) + bv;
            }
            float* dst = g_xprojT + (((size_t)t * D_MODEL + u) * 3 + g) * B_SZ + b0 + ty * 8;
            *(float4*)dst = make_float4(col[0], col[1], col[2], col[3]);
            *(float4*)(dst + 4) = make_float4(col[4], col[5], col[6], col[7]);
        }
    }
}

// ============================================================
// Kernel 2: PERSISTENT GRU — all 96 steps in one launch.
// grid = 128 = 16 unit-groups(23 units = 69 rows, pad 72) x 8 batch-groups(32)
// 128 threads: tid = kq*32 + rg*4 + bg  (warp = kq; 1 warp/SMSP)
// thread tile: 9 rows x 8 batches -> 36 FFMA2 per k.
// h-fill + xT prefetch via cp.async; per-batch-group barrier (16 arrivals).
// smem: wh_s[72][388] + h_s[368][36] + red_s[4][72*36] + xpf[69*32]
// ============================================================
#define WST 388
#define HST 36
#define WH_FLOATS (72 * WST)
#define HSM_FLOATS (D_MODEL * HST)
#define RED_STRIDE (72 * 36)
#define RED_FLOATS (4 * RED_STRIDE)
#define XPF_FLOATS (69 * 32)
#define GRU_SMEM ((WH_FLOATS + HSM_FLOATS + RED_FLOATS + XPF_FLOATS) * 4)

__global__ __launch_bounds__(128, 1)
void gru_persistent_kernel(const float* __restrict__ Wh,
                           const float* __restrict__ bh)
{
    extern __shared__ float sm[];
    float* wh_s  = sm;                                        // [72][388]
    float* h_s   = sm + WH_FLOATS;                            // [368][36]
    float* red_s = sm + WH_FLOATS + HSM_FLOATS;               // [4][72*36]
    float* xpf   = sm + WH_FLOATS + HSM_FLOATS + RED_FLOATS;  // [69][32]

    const int tid = threadIdx.x;
    const int ug  = blockIdx.x >> 3;       // 0..15
    const int bgi = blockIdx.x & 7;        // 0..7
    const int b0 = bgi * 32;
    const int u_base = ug * 23;

    const int kq = tid >> 5;               // 0..3 (warp id)
    const int lane = tid & 31;
    const int rg = lane >> 2;              // 0..7
    const int bg = lane & 3;               // 0..3

    // ---- stage Wh slice ONCE: rows r = ul*3+g (ul 0..22 real, 23 pad) ----
    for (int idx = tid; idx < 72 * 92; idx += 128) {
        int r = idx / 92, q = idx - r * 92;
        int ul = r / 3, g = r - ul * 3;
        float4 v = make_float4(0.f, 0.f, 0.f, 0.f);
        if (ul < 23)
            v = *(const float4*)(Wh + ((size_t)(g * D_MODEL + u_base + ul)) * D_MODEL + q * 4);
        *(float4*)(wh_s + r * WST + q * 4) = v;
    }

    // ---- cache biases for this thread's 6 epilogue outputs (fixed all steps) ----
    float bhr_c[6], bhz_c[6], bhn_c[6];
#pragma unroll
    for (int i = 0; i < 6; i++) {
        int o = tid + i * 128;
        int ul = o >> 5;
        if (ul < 23) {
            int d = u_base + ul;
            bhr_c[i] = bh[d];
            bhz_c[i] = bh[D_MODEL + d];
            bhn_c[i] = bh[2 * D_MODEL + d];
        } else { bhr_c[i] = 0.f; bhz_c[i] = 0.f; bhn_c[i] = 0.f; }
    }

    for (int t = 0; t < T_SZ; t++) {
        const float* xT = g_xprojT + (size_t)t * D_MODEL * 3 * B_SZ;

        // ---- group A: h_{t-1} fill via cp.async ----
        if (t > 0) {
            const float* hp = g_h + (size_t)(t - 1) * D_MODEL * B_SZ;
            for (int idx = tid; idx < D_MODEL * 8; idx += 128) {
                int u = idx >> 3, c = idx & 7;
                cp16(h_s + u * HST + c * 4, hp + (size_t)u * B_SZ + b0 + c * 4);
            }
        }
        cp_commit();
        // ---- group B: xT slice prefetch (consumed in epilogue) ----
        for (int idx = tid; idx < 69 * 8; idx += 128) {
            int row = idx >> 3, c = idx & 7;     // row = ul*3+g
            int ul = row / 3, g = row - ul * 3;
            cp16(xpf + row * 32 + c * 4,
                 xT + ((size_t)(u_base + ul) * 3 + g) * B_SZ + b0 + c * 4);
        }
        cp_commit();

        cp_wait<1>();          // h_s ready (group A done)
        __syncthreads();

        // ---- partial GEMM: 9 rows x 8 batches (4 f32x2 pairs) ----
        unsigned long long acc2[9][4];
#pragma unroll
        for (int j = 0; j < 9; j++)
#pragma unroll
            for (int p = 0; p < 4; p++) acc2[j][p] = 0ull;

        if (t > 0) {
            const float* wp = wh_s + (rg * 9) * WST + kq * 92;
            const float* hp2 = h_s + (kq * 92) * HST + bg * 8;
#pragma unroll 4
            for (int k = 0; k < 92; k++) {
                ulonglong2 hv0 = *(const ulonglong2*)(hp2 + k * HST);
                ulonglong2 hv1 = *(const ulonglong2*)(hp2 + k * HST + 4);
#pragma unroll
                for (int j = 0; j < 9; j++) {
                    unsigned long long wd = dup_f32(wp[j * WST + k]);
                    fma2(acc2[j][0], hv0.x, wd);
                    fma2(acc2[j][1], hv0.y, wd);
                    fma2(acc2[j][2], hv1.x, wd);
                    fma2(acc2[j][3], hv1.y, wd);
                }
            }
        }
        __syncthreads();

        // ---- write partials ----
        {
            float* dst = red_s + kq * RED_STRIDE;
#pragma unroll
            for (int j = 0; j < 9; j++) {
                int row = rg * 9 + j;
                *(ulonglong2*)(dst + row * 36 + bg * 8) =
                    make_ulonglong2(acc2[j][0], acc2[j][1]);
                *(ulonglong2*)(dst + row * 36 + bg * 8 + 4) =
                    make_ulonglong2(acc2[j][2], acc2[j][3]);
            }
        }
        cp_wait<0>();          // xpf ready (long since)
        __syncthreads();

        // ---- parallel epilogue: each thread 6 outputs (unit, batch) ----
        float* hout = g_h + (size_t)t * D_MODEL * B_SZ;
#pragma unroll
        for (int i = 0; i < 6; i++) {
            int o = tid + i * 128;        // 0..767
            int ul = o >> 5;              // 0..23 (23 = pad)
            int b  = o & 31;
            if (ul < 23) {
                int d = u_base + ul;
                int row0 = ul * 3;
                float gsum[3];
#pragma unroll
                for (int g = 0; g < 3; g++) {
                    int row = row0 + g;
                    gsum[g] = red_s[0 * RED_STRIDE + row * 36 + b]
                            + red_s[1 * RED_STRIDE + row * 36 + b]
                            + red_s[2 * RED_STRIDE + row * 36 + b]
                            + red_s[3 * RED_STRIDE + row * 36 + b];
                }
                float gir = xpf[(row0 + 0) * 32 + b];
                float giz = xpf[(row0 + 1) * 32 + b];
                float gin = xpf[(row0 + 2) * 32 + b];
                float rr = fast_sigmoid(gir + gsum[0] + bhr_c[i]);
                float zz = fast_sigmoid(giz + gsum[1] + bhz_c[i]);
                float nn = fast_tanh(gin + rr * (gsum[2] + bhn_c[i]));
                float hprev = (t > 0) ? h_s[d * HST + b] : 0.f;
                hout[(size_t)d * B_SZ + b0 + b] = (1.f - zz) * nn + zz * hprev;
            }
        }

        // ---- per-batch-group barrier (16 arrivals) ----
        __syncthreads();
        if (t < T_SZ - 1) {
            if (tid == 0) {
                __threadfence();                 // release: publish h[t]
                atomicAdd(&g_bars[bgi], 1u);
                unsigned target = 16u * (unsigned)(t + 1);
                while (*(volatile unsigned*)&g_bars[bgi] < target) { }
                __threadfence();                 // acquire
            }
            __syncthreads();
        }
    }
}

// ============================================================
// Kernel 3: heads per-t from g_h: logitsT[t][b][o]
// grid (96, 2), 128 threads (thread = one batch), K chunks of 92
// smem: W_s[31][368] + bias_s[32] + A_s[92][128]
// ============================================================
#define HEAD_SMEM ((31 * 368 + 32 + 92 * 128) * 4)

__global__ void head_kernel(const float* __restrict__ Wc,
                            const float* __restrict__ bc,
                            const float* __restrict__ Wf,
                            const float* __restrict__ bf)
{
    extern __shared__ float sm[];
    float* W_s    = sm;                  // [31][368]
    float* bias_s = sm + 31 * 368;       // [32]
    float* A_s    = bias_s + 32;         // [92][128]

    const int t  = blockIdx.x;
    const int b0 = blockIdx.y * 128;
    const int tid = threadIdx.x;

    for (int idx = tid; idx < 31 * 92; idx += 128) {
        int row = idx / 92, kq = idx % 92;
        const float* src = (row < 2) ? (Wc + (size_t)row * D_MODEL)
                                     : (Wf + (size_t)(row - 2) * D_MODEL);
        float4 v = *(const float4*)(src + kq * 4);
        *(float4*)(W_s + row * D_MODEL + kq * 4) = v;
    }
    if (tid < NOUT) bias_s[tid] = (tid < 2) ? bc[tid] : bf[tid - 2];

    float acc[NOUT];
#pragma unroll
    for (int o = 0; o < NOUT; o++) acc[o] = 0.f;

    for (int c = 0; c < 4; c++) {
        __syncthreads();
        for (int idx = tid; idx < 92 * 32; idx += 128) {
            int r = idx >> 5, cc = idx & 31;
            float4 v = *(const float4*)(g_h +
                         ((size_t)t * D_MODEL + c * 92 + r) * B_SZ + b0 + cc * 4);
            *(float4*)(A_s + r * 128 + cc * 4) = v;
        }
        __syncthreads();
#pragma unroll 4
        for (int kk = 0; kk < 92; kk++) {
            float hv = A_s[kk * 128 + tid];
            const float* wrow = W_s + c * 92 + kk;
#pragma unroll
            for (int o = 0; o < NOUT; o++)
                acc[o] += wrow[o * D_MODEL] * hv;
        }
    }

    float* dst = g_logitsT + ((size_t)t * B_SZ + b0 + tid) * NOUT;
#pragma unroll
    for (int o = 0; o < NOUT; o++)
        dst[o] = acc[o] + bias_s[o];
}

// ============================================================
// Kernel 4: softmax + sigmoid + NMS + argmax
// block per batch (256), thread per t (96); logits from logitsT[t][b][o]
// ============================================================
__global__ void finalize_kernel(float* __restrict__ out)
{
    __shared__ float bg_s[T_SZ];
    const int b = blockIdx.x;
    const int t = threadIdx.x;
    const size_t mi = (size_t)b * T_SZ + t;
    const float* L = g_logitsT + ((size_t)t * B_SZ + b) * NOUT;

    float l0 = L[0], l1 = L[1];
    float mx = fmaxf(l0, l1);
    float e0 = expf(l0 - mx), e1 = expf(l1 - mx);
    float inv = 1.f / (e0 + e1);
    float s0 = e0 * inv, s1 = e1 * inv;
    bg_s[t] = s0;

#pragma unroll
    for (int j = 0; j < NCLS; j++) {
        float v = 1.f / (1.f + expf(-L[2 + j]));
        out[(size_t)M_ROWS * 3 + mi * NCLS + j] = v;
    }
    __syncthreads();

    float wmin = s0;
#pragma unroll
    for (int dt = -2; dt <= 2; dt++) {
        int tt = t + dt;
        if (tt >= 0 && tt < T_SZ) wmin = fminf(wmin, bg_s[tt]);
    }
    bool keep = (s0 == wmin);
    float n0 = keep ? s0 : 0.f;
    float n1 = keep ? s1 : 0.f;

    out[mi] = (n1 > n0) ? 1.f : 0.f;
    out[M_ROWS + mi * 2 + 0] = n0;
    out[M_ROWS + mi * 2 + 1] = n1;
}

// ============================================================
extern "C" void kernel_launch(void* const* d_in, const int* in_sizes, int n_in,
                              void* d_out, int out_size)
{
    const float* features = (const float*)d_in[0];
    // d_in[1] = hand (unused)
    const float* Wi = (const float*)d_in[2];
    const float* Wh = (const float*)d_in[3];
    const float* bi = (const float*)d_in[4];
    const float* bh = (const float*)d_in[5];
    const float* Wc = (const float*)d_in[6];
    const float* bc = (const float*)d_in[7];
    const float* Wf = (const float*)d_in[8];
    const float* bf = (const float*)d_in[9];
    float* out = (float*)d_out;

    cudaFuncSetAttribute(gru_persistent_kernel,
                         cudaFuncAttributeMaxDynamicSharedMemorySize, GRU_SMEM);
    cudaFuncSetAttribute(head_kernel,
                         cudaFuncAttributeMaxDynamicSharedMemorySize, HEAD_SMEM);

    // 0) reset barriers
    init_bar_kernel<<<1, 1>>>();

    // 1) input projection, writing [t][u][g][b] directly
    xproj_kernel<<<dim3(18, 2, T_SZ), 256>>>(features, Wi, bi);

    // 2) recurrence: ONE persistent launch for all 96 steps
    gru_persistent_kernel<<<128, 128, GRU_SMEM>>>(Wh, bh);

    // 3) output heads (reads g_h directly, writes logitsT)
    head_kernel<<<dim3(T_SZ, 2), 128, HEAD_SMEM>>>(Wc, bc, Wf, bf);

    // 4) softmax/sigmoid/NMS/argmax
    finalize_kernel<<<B_SZ, T_SZ>>>(out);
}